// round 1
// baseline (speedup 1.0000x reference)
#include <cuda_runtime.h>

// Problem constants (fixed by the reference)
#define B_DIM 4
#define T_DIM 2048
#define C_DIM 1024
#define H_DIM 16
#define DH    64
#define NTOK  (B_DIM * T_DIM)          // 8192
#define QKV_N (3 * C_DIM)              // 3072

// Scratch (no cudaMalloc allowed): ~134 MB static device globals
__device__ float g_qkv[(size_t)NTOK * QKV_N];   // [8192, 3072] row-major: [.., 3, H, Dh]
__device__ float g_attn[(size_t)NTOK * C_DIM];  // [8192, 1024]

// ---------------------------------------------------------------------------
// Tiled SGEMM:  Cm[M,N] = A[M,K] @ Bm[N,K]^T + bias[N]
// BM=BN=128, BK=16, 256 threads, 8x8 microtile per thread.
// ---------------------------------------------------------------------------
__global__ __launch_bounds__(256) void sgemm_bias_kernel(
    const float* __restrict__ A, const float* __restrict__ Bm,
    const float* __restrict__ bias, float* __restrict__ Cm,
    int M, int N, int K)
{
    const int BM = 128, BN = 128, BK = 16;
    __shared__ float As[BK][BM + 4];
    __shared__ float Bs[BK][BN + 4];

    const int tid = threadIdx.x;
    const int m0 = blockIdx.y * BM;
    const int n0 = blockIdx.x * BN;
    const int tx = tid & 15;      // 0..15 -> 8 columns each
    const int ty = tid >> 4;      // 0..15 -> 8 rows each

    float acc[8][8];
    #pragma unroll
    for (int i = 0; i < 8; i++)
        #pragma unroll
        for (int j = 0; j < 8; j++) acc[i][j] = 0.0f;

    for (int k0 = 0; k0 < K; k0 += BK) {
        // Load A tile (128x16) and B tile (128x16), float4 per thread x2 each
        #pragma unroll
        for (int i = 0; i < 2; i++) {
            int idx = tid + i * 256;          // 0..511
            int row = idx >> 2;               // 0..127
            int kk  = (idx & 3) << 2;         // 0,4,8,12
            float4 va = *(const float4*)(A  + (size_t)(m0 + row) * K + k0 + kk);
            As[kk + 0][row] = va.x; As[kk + 1][row] = va.y;
            As[kk + 2][row] = va.z; As[kk + 3][row] = va.w;
            float4 vb = *(const float4*)(Bm + (size_t)(n0 + row) * K + k0 + kk);
            Bs[kk + 0][row] = vb.x; Bs[kk + 1][row] = vb.y;
            Bs[kk + 2][row] = vb.z; Bs[kk + 3][row] = vb.w;
        }
        __syncthreads();

        #pragma unroll
        for (int kk = 0; kk < BK; kk++) {
            float af[8], bf[8];
            #pragma unroll
            for (int i = 0; i < 8; i++) af[i] = As[kk][ty * 8 + i];
            #pragma unroll
            for (int j = 0; j < 8; j++) bf[j] = Bs[kk][tx * 8 + j];
            #pragma unroll
            for (int i = 0; i < 8; i++)
                #pragma unroll
                for (int j = 0; j < 8; j++)
                    acc[i][j] += af[i] * bf[j];
        }
        __syncthreads();
    }

    // Epilogue: add bias, store
    #pragma unroll
    for (int i = 0; i < 8; i++) {
        int row = m0 + ty * 8 + i;
        #pragma unroll
        for (int j = 0; j < 8; j += 4) {
            int col = n0 + tx * 8 + j;
            float4 o;
            o.x = acc[i][j + 0] + bias[col + 0];
            o.y = acc[i][j + 1] + bias[col + 1];
            o.z = acc[i][j + 2] + bias[col + 2];
            o.w = acc[i][j + 3] + bias[col + 3];
            *(float4*)(Cm + (size_t)row * N + col) = o;
        }
    }
}

// ---------------------------------------------------------------------------
// Causal flash attention, fp32. One thread per query row (q,o in registers),
// 64-key K/V tiles staged in shared memory, online softmax w/ lazy rescale.
// grid = (T/128, H, B), block = 128
// ---------------------------------------------------------------------------
__global__ __launch_bounds__(128) void attn_kernel(
    const float* __restrict__ qkv, float* __restrict__ attn_out)
{
    const int BQ = 128, BKEY = 64;
    __shared__ float Ks[BKEY][DH];
    __shared__ float Vs[BKEY][DH];

    const int b  = blockIdx.z;
    const int h  = blockIdx.y;
    const int q0 = blockIdx.x * BQ;
    const int tid = threadIdx.x;
    const int qi  = q0 + tid;           // this thread's query row
    const float scale = 0.125f;         // 1/sqrt(64)

    // Load q row into registers
    float q[DH];
    const float* qptr = qkv + (size_t)(b * T_DIM + qi) * QKV_N + h * DH;
    #pragma unroll
    for (int d = 0; d < DH; d += 4) {
        float4 v = *(const float4*)(qptr + d);
        q[d] = v.x; q[d + 1] = v.y; q[d + 2] = v.z; q[d + 3] = v.w;
    }

    float o[DH];
    #pragma unroll
    for (int d = 0; d < DH; d++) o[d] = 0.0f;
    float m = -1e30f, l = 0.0f;

    const int ntiles = q0 / BKEY + 2;   // covers keys [0, q0+128)
    for (int t = 0; t < ntiles; t++) {
        const int k0 = t * BKEY;
        // Cooperative K/V tile load: 64 rows x 16 float4 each
        #pragma unroll
        for (int i = 0; i < 8; i++) {
            int idx = tid + i * 128;        // 0..1023
            int row = idx >> 4;
            int d4  = (idx & 15) << 2;
            const float* base = qkv + (size_t)(b * T_DIM + k0 + row) * QKV_N + h * DH + d4;
            *(float4*)(&Ks[row][d4]) = *(const float4*)(base + C_DIM);
            *(float4*)(&Vs[row][d4]) = *(const float4*)(base + 2 * C_DIM);
        }
        __syncthreads();

        const int jmax = min(BKEY, qi - k0 + 1);   // causal bound (may be <=0)
        for (int j = 0; j < jmax; j++) {
            // s = q . K[j]
            const float4* kr = (const float4*)(&Ks[j][0]);
            float s0 = 0.f, s1 = 0.f, s2 = 0.f, s3 = 0.f;
            #pragma unroll
            for (int d4 = 0; d4 < 16; d4++) {
                float4 kk4 = kr[d4];
                s0 += q[d4 * 4 + 0] * kk4.x;
                s1 += q[d4 * 4 + 1] * kk4.y;
                s2 += q[d4 * 4 + 2] * kk4.z;
                s3 += q[d4 * 4 + 3] * kk4.w;
            }
            float s = ((s0 + s1) + (s2 + s3)) * scale;

            if (s > m) {                 // rare (~ln(T) times per row)
                float corr = __expf(m - s);
                l *= corr;
                #pragma unroll
                for (int d = 0; d < DH; d++) o[d] *= corr;
                m = s;
            }
            float p = __expf(s - m);
            l += p;
            const float4* vr = (const float4*)(&Vs[j][0]);
            #pragma unroll
            for (int d4 = 0; d4 < 16; d4++) {
                float4 vv4 = vr[d4];
                o[d4 * 4 + 0] += p * vv4.x;
                o[d4 * 4 + 1] += p * vv4.y;
                o[d4 * 4 + 2] += p * vv4.z;
                o[d4 * 4 + 3] += p * vv4.w;
            }
        }
        __syncthreads();
    }

    const float inv = 1.0f / l;
    float* optr = attn_out + (size_t)(b * T_DIM + qi) * C_DIM + h * DH;
    #pragma unroll
    for (int d = 0; d < DH; d += 4) {
        float4 v;
        v.x = o[d] * inv; v.y = o[d + 1] * inv;
        v.z = o[d + 2] * inv; v.w = o[d + 3] * inv;
        *(float4*)(optr + d) = v;
    }
}

// ---------------------------------------------------------------------------
// Launch: QKV GEMM -> attention -> output GEMM
// ---------------------------------------------------------------------------
extern "C" void kernel_launch(void* const* d_in, const int* in_sizes, int n_in,
                              void* d_out, int out_size)
{
    const float* x    = (const float*)d_in[0];   // [4,2048,1024]
    const float* Wqkv = (const float*)d_in[1];   // [3072,1024]
    const float* bqkv = (const float*)d_in[2];   // [3072]
    const float* Wo   = (const float*)d_in[3];   // [1024,1024]
    const float* bo   = (const float*)d_in[4];   // [1024]
    float* out = (float*)d_out;                  // [4,2048,1024]

    float* qkv;  cudaGetSymbolAddress((void**)&qkv,  g_qkv);
    float* attn; cudaGetSymbolAddress((void**)&attn, g_attn);

    // qkv = x @ Wqkv^T + bqkv   (8192 x 3072)
    sgemm_bias_kernel<<<dim3(QKV_N / 128, NTOK / 128), 256>>>(
        x, Wqkv, bqkv, qkv, NTOK, QKV_N, C_DIM);

    // causal multi-head attention -> g_attn (8192 x 1024)
    attn_kernel<<<dim3(T_DIM / 128, H_DIM, B_DIM), 128>>>(qkv, attn);

    // out = attn @ Wo^T + bo    (8192 x 1024)
    sgemm_bias_kernel<<<dim3(C_DIM / 128, NTOK / 128), 256>>>(
        attn, Wo, bo, out, NTOK, C_DIM, C_DIM);
}

// round 2
// speedup vs baseline: 1.1452x; 1.1452x over previous
#include <cuda_runtime.h>

// Problem constants (fixed by the reference)
#define B_DIM 4
#define T_DIM 2048
#define C_DIM 1024
#define H_DIM 16
#define DH    64
#define NTOK  (B_DIM * T_DIM)          // 8192
#define QKV_N (3 * C_DIM)              // 3072

// Scratch (no cudaMalloc allowed): ~134 MB static device globals
__device__ float g_qkv[(size_t)NTOK * QKV_N];   // [8192, 3072]: [.., 3, H, Dh]
__device__ float g_attn[(size_t)NTOK * C_DIM];  // [8192, 1024]

// ---------------------------------------------------------------------------
// Tiled SGEMM:  Cm[M,N] = A[M,K] @ Bm[N,K]^T + bias[N]
// BM=BN=128, BK=16, 256 threads, 8x8 microtile, global->reg prefetch.
// ---------------------------------------------------------------------------
__global__ __launch_bounds__(256, 2) void sgemm_bias_kernel(
    const float* __restrict__ A, const float* __restrict__ Bm,
    const float* __restrict__ bias, float* __restrict__ Cm,
    int M, int N, int K)
{
    const int BK = 16;
    __shared__ float As[BK][132];
    __shared__ float Bs[BK][132];

    const int tid = threadIdx.x;
    const int m0 = blockIdx.y * 128;
    const int n0 = blockIdx.x * 128;
    const int tx = tid & 15;
    const int ty = tid >> 4;

    float acc[8][8];
    #pragma unroll
    for (int i = 0; i < 8; i++)
        #pragma unroll
        for (int j = 0; j < 8; j++) acc[i][j] = 0.0f;

    float4 pva[2], pvb[2];
    #pragma unroll
    for (int i = 0; i < 2; i++) {
        int idx = tid + i * 256;
        int row = idx >> 2;
        int kk  = (idx & 3) << 2;
        pva[i] = *(const float4*)(A  + (size_t)(m0 + row) * K + kk);
        pvb[i] = *(const float4*)(Bm + (size_t)(n0 + row) * K + kk);
    }

    for (int k0 = 0; k0 < K; k0 += BK) {
        #pragma unroll
        for (int i = 0; i < 2; i++) {
            int idx = tid + i * 256;
            int row = idx >> 2;
            int kk  = (idx & 3) << 2;
            As[kk + 0][row] = pva[i].x; As[kk + 1][row] = pva[i].y;
            As[kk + 2][row] = pva[i].z; As[kk + 3][row] = pva[i].w;
            Bs[kk + 0][row] = pvb[i].x; Bs[kk + 1][row] = pvb[i].y;
            Bs[kk + 2][row] = pvb[i].z; Bs[kk + 3][row] = pvb[i].w;
        }
        __syncthreads();

        if (k0 + BK < K) {
            #pragma unroll
            for (int i = 0; i < 2; i++) {
                int idx = tid + i * 256;
                int row = idx >> 2;
                int kk  = (idx & 3) << 2;
                pva[i] = *(const float4*)(A  + (size_t)(m0 + row) * K + k0 + BK + kk);
                pvb[i] = *(const float4*)(Bm + (size_t)(n0 + row) * K + k0 + BK + kk);
            }
        }

        #pragma unroll
        for (int kk = 0; kk < BK; kk++) {
            float af[8], bf[8];
            #pragma unroll
            for (int i = 0; i < 8; i++) af[i] = As[kk][ty * 8 + i];
            #pragma unroll
            for (int j = 0; j < 8; j++) bf[j] = Bs[kk][tx * 8 + j];
            #pragma unroll
            for (int i = 0; i < 8; i++)
                #pragma unroll
                for (int j = 0; j < 8; j++)
                    acc[i][j] += af[i] * bf[j];
        }
        __syncthreads();
    }

    #pragma unroll
    for (int i = 0; i < 8; i++) {
        int row = m0 + ty * 8 + i;
        #pragma unroll
        for (int j = 0; j < 8; j += 4) {
            int col = n0 + tx * 8 + j;
            float4 o;
            o.x = acc[i][j + 0] + bias[col + 0];
            o.y = acc[i][j + 1] + bias[col + 1];
            o.z = acc[i][j + 2] + bias[col + 2];
            o.w = acc[i][j + 3] + bias[col + 3];
            *(float4*)(Cm + (size_t)row * N + col) = o;
        }
    }
}

// ---------------------------------------------------------------------------
// Register-blocked causal flash attention (fp32).
// Block: 256 threads handles BQ=128 queries for one (b,h).
// Per tile of BK=64 keys:
//   S[128,64] = Qst^T-style GEMM (Q,K stored d-major in smem, 8x4 microtile)
//   online softmax (warp-shuffle row reduce over 16 key-lanes)
//   P staged to smem, O[128,64] += P @ V (second register-tiled GEMM)
// Dynamic smem: Qst[64][132] + Kst[64][68] + Vs[64][68] + Pq[128][68] = 101 KB
// ---------------------------------------------------------------------------
#define QS 132
#define KS 68
#define VS 68
#define PS 68
#define ATTN_SMEM ((64*QS + 64*KS + 64*VS + 128*PS) * sizeof(float))

__global__ __launch_bounds__(256, 2) void attn_kernel(
    const float* __restrict__ qkv, float* __restrict__ attn_out)
{
    extern __shared__ float sm[];
    float* Qst = sm;                    // [64][132]  (d-major, scaled)
    float* Kst = Qst + 64 * QS;         // [64][68]   (d-major)
    float* Vsm = Kst + 64 * KS;         // [64][68]   (k-major)
    float* Pq  = Vsm + 64 * VS;         // [128][68]  (q-major)

    const int b  = blockIdx.z;
    const int h  = blockIdx.y;
    const int q0 = ((int)gridDim.x - 1 - (int)blockIdx.x) * 128;  // heavy blocks first
    const int tid = threadIdx.x;
    const int tx = tid & 15;            // key / dim group (4 each)
    const int ty = tid >> 4;            // query group (8 each)
    const float scale = 0.125f;         // 1/sqrt(64)

    // Load Q tile (128 x 64), store transposed d-major, scaled.
    #pragma unroll
    for (int r = 0; r < 8; r++) {
        int idx = tid + r * 256;        // 0..2047
        int row = idx >> 4;             // 0..127
        int d4  = (idx & 15) << 2;
        float4 v = *(const float4*)(qkv + ((size_t)(b * T_DIM + q0 + row)) * QKV_N + h * DH + d4);
        Qst[(d4 + 0) * QS + row] = v.x * scale;
        Qst[(d4 + 1) * QS + row] = v.y * scale;
        Qst[(d4 + 2) * QS + row] = v.z * scale;
        Qst[(d4 + 3) * QS + row] = v.w * scale;
    }

    float Ov[8][4];
    float mrow[8], lrow[8];
    #pragma unroll
    for (int i = 0; i < 8; i++) {
        mrow[i] = -1e30f; lrow[i] = 0.0f;
        #pragma unroll
        for (int j = 0; j < 4; j++) Ov[i][j] = 0.0f;
    }

    const int kend = q0 + 128;
    for (int k0 = 0; k0 < kend; k0 += 64) {
        __syncthreads();   // prev PV reads of Kst/Vsm/Pq complete

        // Load K (d-major transpose) and V (k-major), 64 x 64 each.
        #pragma unroll
        for (int r = 0; r < 4; r++) {
            int idx = tid + r * 256;    // 0..1023
            int row = idx >> 4;         // 0..63
            int d4  = (idx & 15) << 2;
            const float* base = qkv + ((size_t)(b * T_DIM + k0 + row)) * QKV_N + h * DH + d4;
            float4 kv = *(const float4*)(base + C_DIM);
            Kst[(d4 + 0) * KS + row] = kv.x;
            Kst[(d4 + 1) * KS + row] = kv.y;
            Kst[(d4 + 2) * KS + row] = kv.z;
            Kst[(d4 + 3) * KS + row] = kv.w;
            *(float4*)(Vsm + row * VS + d4) = *(const float4*)(base + 2 * C_DIM);
        }
        __syncthreads();

        // S = Q @ K^T  (thread: 8 queries x 4 keys)
        float S[8][4];
        #pragma unroll
        for (int i = 0; i < 8; i++)
            #pragma unroll
            for (int j = 0; j < 4; j++) S[i][j] = 0.0f;

        #pragma unroll 8
        for (int d = 0; d < 64; d++) {
            float4 a0 = *(const float4*)(Qst + d * QS + ty * 8);
            float4 a1 = *(const float4*)(Qst + d * QS + ty * 8 + 4);
            float4 bv = *(const float4*)(Kst + d * KS + tx * 4);
            float af[8] = {a0.x, a0.y, a0.z, a0.w, a1.x, a1.y, a1.z, a1.w};
            float bf[4] = {bv.x, bv.y, bv.z, bv.w};
            #pragma unroll
            for (int i = 0; i < 8; i++)
                #pragma unroll
                for (int j = 0; j < 4; j++)
                    S[i][j] += af[i] * bf[j];
        }

        // Causal mask (only diagonal tiles)
        if (k0 + 64 > q0) {
            #pragma unroll
            for (int i = 0; i < 8; i++) {
                int qi = q0 + ty * 8 + i;
                #pragma unroll
                for (int j = 0; j < 4; j++)
                    if (k0 + tx * 4 + j > qi) S[i][j] = -1e30f;
            }
        }

        // Online softmax per query row; P -> smem
        #pragma unroll
        for (int i = 0; i < 8; i++) {
            float rmax = fmaxf(fmaxf(S[i][0], S[i][1]), fmaxf(S[i][2], S[i][3]));
            rmax = fmaxf(rmax, __shfl_xor_sync(0xffffffffu, rmax, 1));
            rmax = fmaxf(rmax, __shfl_xor_sync(0xffffffffu, rmax, 2));
            rmax = fmaxf(rmax, __shfl_xor_sync(0xffffffffu, rmax, 4));
            rmax = fmaxf(rmax, __shfl_xor_sync(0xffffffffu, rmax, 8));
            float newm = fmaxf(mrow[i], rmax);
            float corr = __expf(mrow[i] - newm);
            float p0 = __expf(S[i][0] - newm);
            float p1 = __expf(S[i][1] - newm);
            float p2 = __expf(S[i][2] - newm);
            float p3 = __expf(S[i][3] - newm);
            float rsum = (p0 + p1) + (p2 + p3);
            rsum += __shfl_xor_sync(0xffffffffu, rsum, 1);
            rsum += __shfl_xor_sync(0xffffffffu, rsum, 2);
            rsum += __shfl_xor_sync(0xffffffffu, rsum, 4);
            rsum += __shfl_xor_sync(0xffffffffu, rsum, 8);
            lrow[i] = lrow[i] * corr + rsum;
            mrow[i] = newm;
            #pragma unroll
            for (int j = 0; j < 4; j++) Ov[i][j] *= corr;
            *(float4*)(Pq + (ty * 8 + i) * PS + tx * 4) = make_float4(p0, p1, p2, p3);
        }
        __syncthreads();

        // O += P @ V  (thread: 8 queries x 4 dims)
        #pragma unroll 2
        for (int k4 = 0; k4 < 16; k4++) {
            float pvf[8][4];
            #pragma unroll
            for (int i = 0; i < 8; i++)
                *(float4*)(&pvf[i][0]) = *(const float4*)(Pq + (ty * 8 + i) * PS + k4 * 4);
            #pragma unroll
            for (int kk = 0; kk < 4; kk++) {
                float4 vv = *(const float4*)(Vsm + (k4 * 4 + kk) * VS + tx * 4);
                #pragma unroll
                for (int i = 0; i < 8; i++) {
                    Ov[i][0] += pvf[i][kk] * vv.x;
                    Ov[i][1] += pvf[i][kk] * vv.y;
                    Ov[i][2] += pvf[i][kk] * vv.z;
                    Ov[i][3] += pvf[i][kk] * vv.w;
                }
            }
        }
    }

    // Epilogue: normalize and store
    #pragma unroll
    for (int i = 0; i < 8; i++) {
        float inv = 1.0f / lrow[i];
        float4 o;
        o.x = Ov[i][0] * inv; o.y = Ov[i][1] * inv;
        o.z = Ov[i][2] * inv; o.w = Ov[i][3] * inv;
        *(float4*)(attn_out + ((size_t)(b * T_DIM + q0 + ty * 8 + i)) * C_DIM + h * DH + tx * 4) = o;
    }
}

// ---------------------------------------------------------------------------
// Launch: QKV GEMM -> attention -> output GEMM
// ---------------------------------------------------------------------------
extern "C" void kernel_launch(void* const* d_in, const int* in_sizes, int n_in,
                              void* d_out, int out_size)
{
    const float* x    = (const float*)d_in[0];   // [4,2048,1024]
    const float* Wqkv = (const float*)d_in[1];   // [3072,1024]
    const float* bqkv = (const float*)d_in[2];   // [3072]
    const float* Wo   = (const float*)d_in[3];   // [1024,1024]
    const float* bo   = (const float*)d_in[4];   // [1024]
    float* out = (float*)d_out;                  // [4,2048,1024]

    float* qkv;  cudaGetSymbolAddress((void**)&qkv,  g_qkv);
    float* attn; cudaGetSymbolAddress((void**)&attn, g_attn);

    cudaFuncSetAttribute(attn_kernel, cudaFuncAttributeMaxDynamicSharedMemorySize,
                         (int)ATTN_SMEM);

    // qkv = x @ Wqkv^T + bqkv   (8192 x 3072)
    sgemm_bias_kernel<<<dim3(QKV_N / 128, NTOK / 128), 256>>>(
        x, Wqkv, bqkv, qkv, NTOK, QKV_N, C_DIM);

    // causal multi-head attention -> g_attn (8192 x 1024)
    attn_kernel<<<dim3(T_DIM / 128, H_DIM, B_DIM), 256, ATTN_SMEM>>>(qkv, attn);

    // out = attn @ Wo^T + bo    (8192 x 1024)
    sgemm_bias_kernel<<<dim3(C_DIM / 128, NTOK / 128), 256>>>(
        attn, Wo, bo, out, NTOK, C_DIM, C_DIM);
}

// round 4
// speedup vs baseline: 1.9019x; 1.6608x over previous
#include <cuda_runtime.h>
#include <cuda_bf16.h>
#include <cstdint>

// Problem constants
#define B_DIM 4
#define T_DIM 2048
#define C_DIM 1024
#define H_DIM 16
#define DH    64
#define NTOK  8192
#define QKV_N 3072

// Static device scratch (no cudaMalloc allowed)
__device__ float         g_qkv[(size_t)NTOK * QKV_N];
__device__ __nv_bfloat16 g_xhi[(size_t)NTOK * C_DIM];
__device__ __nv_bfloat16 g_xlo[(size_t)NTOK * C_DIM];
__device__ __nv_bfloat16 g_wqkv_hi[(size_t)QKV_N * C_DIM];
__device__ __nv_bfloat16 g_wqkv_lo[(size_t)QKV_N * C_DIM];
__device__ __nv_bfloat16 g_wo_hi[(size_t)C_DIM * C_DIM];
__device__ __nv_bfloat16 g_wo_lo[(size_t)C_DIM * C_DIM];
__device__ __nv_bfloat16 g_ahi[(size_t)NTOK * C_DIM];
__device__ __nv_bfloat16 g_alo[(size_t)NTOK * C_DIM];

// ---------------------------------------------------------------------------
// Helpers (base sm_100 features only: cp.async, ldmatrix, mma.sync)
// ---------------------------------------------------------------------------
static __device__ __forceinline__ uint32_t smem_u32(const void* p) {
    uint32_t a;
    asm("{ .reg .u64 t; cvta.to.shared.u64 t, %1; cvt.u32.u64 %0, t; }"
        : "=r"(a) : "l"(p));
    return a;
}
static __device__ __forceinline__ void cp_async16(uint32_t s, const void* g) {
    asm volatile("cp.async.ca.shared.global [%0], [%1], 16;" :: "r"(s), "l"(g));
}
static __device__ __forceinline__ void cp_commit() {
    asm volatile("cp.async.commit_group;" ::: "memory");
}
template <int N> static __device__ __forceinline__ void cp_wait() {
    asm volatile("cp.async.wait_group %0;" :: "n"(N) : "memory");
}
static __device__ __forceinline__ void ldsm4(uint32_t* r, uint32_t addr) {
    asm volatile("ldmatrix.sync.aligned.m8n8.x4.shared.b16 {%0,%1,%2,%3}, [%4];"
        : "=r"(r[0]), "=r"(r[1]), "=r"(r[2]), "=r"(r[3]) : "r"(addr));
}
static __device__ __forceinline__ void mma16816(float* c, const uint32_t* a,
                                                const uint32_t* b) {
    asm volatile("mma.sync.aligned.m16n8k16.row.col.f32.bf16.bf16.f32 "
        "{%0,%1,%2,%3}, {%4,%5,%6,%7}, {%8,%9}, {%0,%1,%2,%3};"
        : "+f"(c[0]), "+f"(c[1]), "+f"(c[2]), "+f"(c[3])
        : "r"(a[0]), "r"(a[1]), "r"(a[2]), "r"(a[3]), "r"(b[0]), "r"(b[1]));
}

// ---------------------------------------------------------------------------
// Split fp32 -> bf16 hi/lo (memory-bound)
// ---------------------------------------------------------------------------
__global__ __launch_bounds__(256) void split_kernel(
    const float* __restrict__ src, __nv_bfloat16* __restrict__ hi,
    __nv_bfloat16* __restrict__ lo, int n4)
{
    int i = blockIdx.x * blockDim.x + threadIdx.x;
    if (i >= n4) return;
    float4 v = ((const float4*)src)[i];
    __nv_bfloat16 h0 = __float2bfloat16(v.x), h1 = __float2bfloat16(v.y);
    __nv_bfloat16 h2 = __float2bfloat16(v.z), h3 = __float2bfloat16(v.w);
    __nv_bfloat16 l0 = __float2bfloat16(v.x - __bfloat162float(h0));
    __nv_bfloat16 l1 = __float2bfloat16(v.y - __bfloat162float(h1));
    __nv_bfloat16 l2 = __float2bfloat16(v.z - __bfloat162float(h2));
    __nv_bfloat16 l3 = __float2bfloat16(v.w - __bfloat162float(h3));
    ((__nv_bfloat162*)hi)[i * 2 + 0] = __nv_bfloat162(h0, h1);
    ((__nv_bfloat162*)hi)[i * 2 + 1] = __nv_bfloat162(h2, h3);
    ((__nv_bfloat162*)lo)[i * 2 + 0] = __nv_bfloat162(l0, l1);
    ((__nv_bfloat162*)lo)[i * 2 + 1] = __nv_bfloat162(l2, l3);
}

// ---------------------------------------------------------------------------
// bf16x3 HMMA GEMM: C[M,N] = (Ahi+Alo)[M,K] @ (Bhi+Blo)[N,K]^T + bias[N]
// CTA 128x128, 8 warps (4m x 2n), warp tile 32x64, Kc=32 double-buffered.
// smem rows: 32 bf16 data padded to 80B -> conflict-free ldmatrix.
// ---------------------------------------------------------------------------
#define KC      32
#define TSTR    80                 // smem row stride bytes
#define TILE_B  (128 * TSTR)       // 10240 B per operand tile
#define BUF_B   (4 * TILE_B)       // Ahi,Alo,Bhi,Blo
#define G_SMEM  (2 * BUF_B)        // 81920 B

__global__ __launch_bounds__(256, 2) void gemm_bf16x3_kernel(
    const __nv_bfloat16* __restrict__ Ahi, const __nv_bfloat16* __restrict__ Alo,
    const __nv_bfloat16* __restrict__ Bhi, const __nv_bfloat16* __restrict__ Blo,
    const float* __restrict__ bias, float* __restrict__ C,
    int M, int N, int K)
{
    extern __shared__ char smraw[];
    const uint32_t sb = smem_u32(smraw);

    const int tid  = threadIdx.x;
    const int lane = tid & 31;
    const int wid  = tid >> 5;
    const int wm   = wid >> 1;          // 0..3 -> m offset wm*32
    const int wn   = wid & 1;           // 0..1 -> n offset wn*64
    const int m0 = blockIdx.y * 128;
    const int n0 = blockIdx.x * 128;

    // ldmatrix per-lane offsets
    const uint32_t a_row = lane & 15;
    const uint32_t a_kof = ((lane >> 4) << 3) * 2;          // bytes
    const uint32_t b_row = (lane & 7) | (((lane >> 4) & 1) << 3);
    const uint32_t b_kof = (((lane >> 3) & 1) << 3) * 2;    // bytes

    float acc[2][8][4];
    #pragma unroll
    for (int i = 0; i < 2; i++)
        #pragma unroll
        for (int j = 0; j < 8; j++)
            #pragma unroll
            for (int c = 0; c < 4; c++) acc[i][j][c] = 0.0f;

    // Chunk loader: 4 tiles x 128 rows x 4 segs of 16B = 2048 cp.async / 256 thr
    auto load_chunk = [&](int c, int b) {
        const int k0 = c * KC;
        const uint32_t bufb = sb + b * BUF_B;
        #pragma unroll
        for (int it = 0; it < 8; it++) {
            int idx = tid + it * 256;     // 0..2047
            int t   = idx >> 9;           // 0..3
            int w   = idx & 511;
            int row = w >> 2;
            int seg = w & 3;
            const __nv_bfloat16* gp;
            if (t == 0)      gp = Ahi + (size_t)(m0 + row) * K + k0 + seg * 8;
            else if (t == 1) gp = Alo + (size_t)(m0 + row) * K + k0 + seg * 8;
            else if (t == 2) gp = Bhi + (size_t)(n0 + row) * K + k0 + seg * 8;
            else             gp = Blo + (size_t)(n0 + row) * K + k0 + seg * 8;
            cp_async16(bufb + t * TILE_B + row * TSTR + seg * 16, gp);
        }
        cp_commit();
    };

    const int nch = K / KC;
    load_chunk(0, 0);

    for (int i = 0; i < nch; i++) {
        if (i + 1 < nch) { load_chunk(i + 1, (i + 1) & 1); cp_wait<1>(); }
        else             { cp_wait<0>(); }
        __syncthreads();

        const uint32_t bufb = sb + (i & 1) * BUF_B;
        const uint32_t Aht = bufb;
        const uint32_t Alt = bufb + TILE_B;
        const uint32_t Bht = bufb + 2 * TILE_B;
        const uint32_t Blt = bufb + 3 * TILE_B;

        #pragma unroll
        for (int ks = 0; ks < 2; ks++) {
            const uint32_t kb = ks * 32;  // byte offset of k-step (16 bf16)
            uint32_t ah[2][4], al[2][4];
            #pragma unroll
            for (int mi = 0; mi < 2; mi++) {
                uint32_t roff = (wm * 32 + mi * 16 + a_row) * TSTR + kb + a_kof;
                ldsm4(ah[mi], Aht + roff);
                ldsm4(al[mi], Alt + roff);
            }
            #pragma unroll
            for (int njp = 0; njp < 4; njp++) {
                uint32_t bh[4], bl[4];
                uint32_t roff = (wn * 64 + njp * 16 + b_row) * TSTR + kb + b_kof;
                ldsm4(bh, Bht + roff);
                ldsm4(bl, Blt + roff);
                #pragma unroll
                for (int mi = 0; mi < 2; mi++) {
                    mma16816(acc[mi][2 * njp],     ah[mi], bh);
                    mma16816(acc[mi][2 * njp],     al[mi], bh);
                    mma16816(acc[mi][2 * njp],     ah[mi], bl);
                    mma16816(acc[mi][2 * njp + 1], ah[mi], bh + 2);
                    mma16816(acc[mi][2 * njp + 1], al[mi], bh + 2);
                    mma16816(acc[mi][2 * njp + 1], ah[mi], bl + 2);
                }
            }
        }
        __syncthreads();
    }

    // Epilogue: c0,c1 -> row, c2,c3 -> row+8; col pair (lane&3)*2
    #pragma unroll
    for (int mi = 0; mi < 2; mi++) {
        int row = m0 + wm * 32 + mi * 16 + (lane >> 2);
        #pragma unroll
        for (int nj = 0; nj < 8; nj++) {
            int col = n0 + wn * 64 + nj * 8 + (lane & 3) * 2;
            float bx = bias[col], by = bias[col + 1];
            float2 v0 = make_float2(acc[mi][nj][0] + bx, acc[mi][nj][1] + by);
            float2 v1 = make_float2(acc[mi][nj][2] + bx, acc[mi][nj][3] + by);
            *(float2*)(C + (size_t)row * N + col) = v0;
            *(float2*)(C + (size_t)(row + 8) * N + col) = v1;
        }
    }
}

// ---------------------------------------------------------------------------
// Register-blocked causal flash attention (fp32), epilogue emits bf16 hi/lo.
// ---------------------------------------------------------------------------
#define QS 132
#define KS 68
#define VS 68
#define PS 68
#define ATTN_SMEM ((64*QS + 64*KS + 64*VS + 128*PS) * sizeof(float))

__global__ __launch_bounds__(256, 2) void attn_kernel(
    const float* __restrict__ qkv,
    __nv_bfloat16* __restrict__ out_hi, __nv_bfloat16* __restrict__ out_lo)
{
    extern __shared__ float sm[];
    float* Qst = sm;
    float* Kst = Qst + 64 * QS;
    float* Vsm = Kst + 64 * KS;
    float* Pq  = Vsm + 64 * VS;

    const int b  = blockIdx.z;
    const int h  = blockIdx.y;
    const int q0 = ((int)gridDim.x - 1 - (int)blockIdx.x) * 128;
    const int tid = threadIdx.x;
    const int tx = tid & 15;
    const int ty = tid >> 4;
    const float scale = 0.125f;

    #pragma unroll
    for (int r = 0; r < 8; r++) {
        int idx = tid + r * 256;
        int row = idx >> 4;
        int d4  = (idx & 15) << 2;
        float4 v = *(const float4*)(qkv + ((size_t)(b * T_DIM + q0 + row)) * QKV_N + h * DH + d4);
        Qst[(d4 + 0) * QS + row] = v.x * scale;
        Qst[(d4 + 1) * QS + row] = v.y * scale;
        Qst[(d4 + 2) * QS + row] = v.z * scale;
        Qst[(d4 + 3) * QS + row] = v.w * scale;
    }

    float Ov[8][4];
    float mrow[8], lrow[8];
    #pragma unroll
    for (int i = 0; i < 8; i++) {
        mrow[i] = -1e30f; lrow[i] = 0.0f;
        #pragma unroll
        for (int j = 0; j < 4; j++) Ov[i][j] = 0.0f;
    }

    const int kend = q0 + 128;
    for (int k0 = 0; k0 < kend; k0 += 64) {
        __syncthreads();
        #pragma unroll
        for (int r = 0; r < 4; r++) {
            int idx = tid + r * 256;
            int row = idx >> 4;
            int d4  = (idx & 15) << 2;
            const float* base = qkv + ((size_t)(b * T_DIM + k0 + row)) * QKV_N + h * DH + d4;
            float4 kv = *(const float4*)(base + C_DIM);
            Kst[(d4 + 0) * KS + row] = kv.x;
            Kst[(d4 + 1) * KS + row] = kv.y;
            Kst[(d4 + 2) * KS + row] = kv.z;
            Kst[(d4 + 3) * KS + row] = kv.w;
            *(float4*)(Vsm + row * VS + d4) = *(const float4*)(base + 2 * C_DIM);
        }
        __syncthreads();

        float S[8][4];
        #pragma unroll
        for (int i = 0; i < 8; i++)
            #pragma unroll
            for (int j = 0; j < 4; j++) S[i][j] = 0.0f;

        #pragma unroll 8
        for (int d = 0; d < 64; d++) {
            float4 a0 = *(const float4*)(Qst + d * QS + ty * 8);
            float4 a1 = *(const float4*)(Qst + d * QS + ty * 8 + 4);
            float4 bv = *(const float4*)(Kst + d * KS + tx * 4);
            float af[8] = {a0.x, a0.y, a0.z, a0.w, a1.x, a1.y, a1.z, a1.w};
            float bf[4] = {bv.x, bv.y, bv.z, bv.w};
            #pragma unroll
            for (int i = 0; i < 8; i++)
                #pragma unroll
                for (int j = 0; j < 4; j++)
                    S[i][j] += af[i] * bf[j];
        }

        if (k0 + 64 > q0) {
            #pragma unroll
            for (int i = 0; i < 8; i++) {
                int qi = q0 + ty * 8 + i;
                #pragma unroll
                for (int j = 0; j < 4; j++)
                    if (k0 + tx * 4 + j > qi) S[i][j] = -1e30f;
            }
        }

        #pragma unroll
        for (int i = 0; i < 8; i++) {
            float rmax = fmaxf(fmaxf(S[i][0], S[i][1]), fmaxf(S[i][2], S[i][3]));
            rmax = fmaxf(rmax, __shfl_xor_sync(0xffffffffu, rmax, 1));
            rmax = fmaxf(rmax, __shfl_xor_sync(0xffffffffu, rmax, 2));
            rmax = fmaxf(rmax, __shfl_xor_sync(0xffffffffu, rmax, 4));
            rmax = fmaxf(rmax, __shfl_xor_sync(0xffffffffu, rmax, 8));
            float newm = fmaxf(mrow[i], rmax);
            float corr = __expf(mrow[i] - newm);
            float p0 = __expf(S[i][0] - newm);
            float p1 = __expf(S[i][1] - newm);
            float p2 = __expf(S[i][2] - newm);
            float p3 = __expf(S[i][3] - newm);
            float rsum = (p0 + p1) + (p2 + p3);
            rsum += __shfl_xor_sync(0xffffffffu, rsum, 1);
            rsum += __shfl_xor_sync(0xffffffffu, rsum, 2);
            rsum += __shfl_xor_sync(0xffffffffu, rsum, 4);
            rsum += __shfl_xor_sync(0xffffffffu, rsum, 8);
            lrow[i] = lrow[i] * corr + rsum;
            mrow[i] = newm;
            #pragma unroll
            for (int j = 0; j < 4; j++) Ov[i][j] *= corr;
            *(float4*)(Pq + (ty * 8 + i) * PS + tx * 4) = make_float4(p0, p1, p2, p3);
        }
        __syncthreads();

        #pragma unroll 2
        for (int k4 = 0; k4 < 16; k4++) {
            float pvf[8][4];
            #pragma unroll
            for (int i = 0; i < 8; i++)
                *(float4*)(&pvf[i][0]) = *(const float4*)(Pq + (ty * 8 + i) * PS + k4 * 4);
            #pragma unroll
            for (int kk = 0; kk < 4; kk++) {
                float4 vv = *(const float4*)(Vsm + (k4 * 4 + kk) * VS + tx * 4);
                #pragma unroll
                for (int i = 0; i < 8; i++) {
                    Ov[i][0] += pvf[i][kk] * vv.x;
                    Ov[i][1] += pvf[i][kk] * vv.y;
                    Ov[i][2] += pvf[i][kk] * vv.z;
                    Ov[i][3] += pvf[i][kk] * vv.w;
                }
            }
        }
    }

    #pragma unroll
    for (int i = 0; i < 8; i++) {
        float inv = 1.0f / lrow[i];
        size_t base = ((size_t)(b * T_DIM + q0 + ty * 8 + i)) * C_DIM + h * DH + tx * 4;
        float v[4];
        #pragma unroll
        for (int j = 0; j < 4; j++) v[j] = Ov[i][j] * inv;
        __nv_bfloat16 h0 = __float2bfloat16(v[0]), h1 = __float2bfloat16(v[1]);
        __nv_bfloat16 h2 = __float2bfloat16(v[2]), h3 = __float2bfloat16(v[3]);
        __nv_bfloat16 l0 = __float2bfloat16(v[0] - __bfloat162float(h0));
        __nv_bfloat16 l1 = __float2bfloat16(v[1] - __bfloat162float(h1));
        __nv_bfloat16 l2 = __float2bfloat16(v[2] - __bfloat162float(h2));
        __nv_bfloat16 l3 = __float2bfloat16(v[3] - __bfloat162float(h3));
        *(__nv_bfloat162*)(out_hi + base)     = __nv_bfloat162(h0, h1);
        *(__nv_bfloat162*)(out_hi + base + 2) = __nv_bfloat162(h2, h3);
        *(__nv_bfloat162*)(out_lo + base)     = __nv_bfloat162(l0, l1);
        *(__nv_bfloat162*)(out_lo + base + 2) = __nv_bfloat162(l2, l3);
    }
}

// ---------------------------------------------------------------------------
// Launch
// ---------------------------------------------------------------------------
extern "C" void kernel_launch(void* const* d_in, const int* in_sizes, int n_in,
                              void* d_out, int out_size)
{
    const float* x    = (const float*)d_in[0];
    const float* Wqkv = (const float*)d_in[1];
    const float* bqkv = (const float*)d_in[2];
    const float* Wo   = (const float*)d_in[3];
    const float* bo   = (const float*)d_in[4];
    float* out = (float*)d_out;

    float *qkv;
    __nv_bfloat16 *xhi, *xlo, *wqh, *wql, *woh, *wol, *ahi, *alo;
    cudaGetSymbolAddress((void**)&qkv, g_qkv);
    cudaGetSymbolAddress((void**)&xhi, g_xhi);
    cudaGetSymbolAddress((void**)&xlo, g_xlo);
    cudaGetSymbolAddress((void**)&wqh, g_wqkv_hi);
    cudaGetSymbolAddress((void**)&wql, g_wqkv_lo);
    cudaGetSymbolAddress((void**)&woh, g_wo_hi);
    cudaGetSymbolAddress((void**)&wol, g_wo_lo);
    cudaGetSymbolAddress((void**)&ahi, g_ahi);
    cudaGetSymbolAddress((void**)&alo, g_alo);

    cudaFuncSetAttribute(gemm_bf16x3_kernel,
                         cudaFuncAttributeMaxDynamicSharedMemorySize, G_SMEM);
    cudaFuncSetAttribute(attn_kernel,
                         cudaFuncAttributeMaxDynamicSharedMemorySize, (int)ATTN_SMEM);

    split_kernel<<<(NTOK * C_DIM / 4 + 255) / 256, 256>>>(x, xhi, xlo, NTOK * C_DIM / 4);
    split_kernel<<<(QKV_N * C_DIM / 4 + 255) / 256, 256>>>(Wqkv, wqh, wql, QKV_N * C_DIM / 4);
    split_kernel<<<(C_DIM * C_DIM / 4 + 255) / 256, 256>>>(Wo, woh, wol, C_DIM * C_DIM / 4);

    gemm_bf16x3_kernel<<<dim3(QKV_N / 128, NTOK / 128), 256, G_SMEM>>>(
        xhi, xlo, wqh, wql, bqkv, qkv, NTOK, QKV_N, C_DIM);

    attn_kernel<<<dim3(T_DIM / 128, H_DIM, B_DIM), 256, ATTN_SMEM>>>(qkv, ahi, alo);

    gemm_bf16x3_kernel<<<dim3(C_DIM / 128, NTOK / 128), 256, G_SMEM>>>(
        ahi, alo, woh, wol, bo, out, NTOK, C_DIM, C_DIM);
}

// round 5
// speedup vs baseline: 3.0300x; 1.5932x over previous
#include <cuda_runtime.h>
#include <cuda_bf16.h>
#include <cstdint>

// Problem constants
#define B_DIM 4
#define T_DIM 2048
#define C_DIM 1024
#define H_DIM 16
#define DH    64
#define NTOK  8192
#define QKV_N 3072

// Static device scratch (no cudaMalloc allowed)
__device__ __nv_bfloat16 g_qkvhi[(size_t)NTOK * QKV_N];
__device__ __nv_bfloat16 g_qkvlo[(size_t)NTOK * QKV_N];
__device__ __nv_bfloat16 g_xhi[(size_t)NTOK * C_DIM];
__device__ __nv_bfloat16 g_xlo[(size_t)NTOK * C_DIM];
__device__ __nv_bfloat16 g_wqkv_hi[(size_t)QKV_N * C_DIM];
__device__ __nv_bfloat16 g_wqkv_lo[(size_t)QKV_N * C_DIM];
__device__ __nv_bfloat16 g_wo_hi[(size_t)C_DIM * C_DIM];
__device__ __nv_bfloat16 g_wo_lo[(size_t)C_DIM * C_DIM];
__device__ __nv_bfloat16 g_ahi[(size_t)NTOK * C_DIM];
__device__ __nv_bfloat16 g_alo[(size_t)NTOK * C_DIM];

// ---------------------------------------------------------------------------
// Helpers (base sm_100: cp.async, ldmatrix, mma.sync)
// ---------------------------------------------------------------------------
static __device__ __forceinline__ uint32_t smem_u32(const void* p) {
    uint32_t a;
    asm("{ .reg .u64 t; cvta.to.shared.u64 t, %1; cvt.u32.u64 %0, t; }"
        : "=r"(a) : "l"(p));
    return a;
}
static __device__ __forceinline__ void cp_async16(uint32_t s, const void* g) {
    asm volatile("cp.async.ca.shared.global [%0], [%1], 16;" :: "r"(s), "l"(g));
}
static __device__ __forceinline__ void cp_commit() {
    asm volatile("cp.async.commit_group;" ::: "memory");
}
template <int N> static __device__ __forceinline__ void cp_wait() {
    asm volatile("cp.async.wait_group %0;" :: "n"(N) : "memory");
}
static __device__ __forceinline__ void ldsm4(uint32_t* r, uint32_t addr) {
    asm volatile("ldmatrix.sync.aligned.m8n8.x4.shared.b16 {%0,%1,%2,%3}, [%4];"
        : "=r"(r[0]), "=r"(r[1]), "=r"(r[2]), "=r"(r[3]) : "r"(addr));
}
static __device__ __forceinline__ void ldsm4t(uint32_t* r, uint32_t addr) {
    asm volatile("ldmatrix.sync.aligned.m8n8.x4.trans.shared.b16 {%0,%1,%2,%3}, [%4];"
        : "=r"(r[0]), "=r"(r[1]), "=r"(r[2]), "=r"(r[3]) : "r"(addr));
}
static __device__ __forceinline__ void mma16816(float* c, const uint32_t* a,
                                                const uint32_t* b) {
    asm volatile("mma.sync.aligned.m16n8k16.row.col.f32.bf16.bf16.f32 "
        "{%0,%1,%2,%3}, {%4,%5,%6,%7}, {%8,%9}, {%0,%1,%2,%3};"
        : "+f"(c[0]), "+f"(c[1]), "+f"(c[2]), "+f"(c[3])
        : "r"(a[0]), "r"(a[1]), "r"(a[2]), "r"(a[3]), "r"(b[0]), "r"(b[1]));
}
// Split two fp32 into packed bf16x2 hi + bf16x2 lo (lo = residual)
static __device__ __forceinline__ void split2(float a, float b,
                                              uint32_t& hi, uint32_t& lo) {
    __nv_bfloat16 ha = __float2bfloat16(a), hb = __float2bfloat16(b);
    float ra = a - __bfloat162float(ha);
    float rb = b - __bfloat162float(hb);
    __nv_bfloat162 H(ha, hb);
    __nv_bfloat162 L(__float2bfloat16(ra), __float2bfloat16(rb));
    hi = *(uint32_t*)&H; lo = *(uint32_t*)&L;
}

// ---------------------------------------------------------------------------
// Split fp32 -> bf16 hi/lo (memory-bound)
// ---------------------------------------------------------------------------
__global__ __launch_bounds__(256) void split_kernel(
    const float* __restrict__ src, __nv_bfloat16* __restrict__ hi,
    __nv_bfloat16* __restrict__ lo, int n4)
{
    int i = blockIdx.x * blockDim.x + threadIdx.x;
    if (i >= n4) return;
    float4 v = ((const float4*)src)[i];
    uint32_t h0, l0, h1, l1;
    split2(v.x, v.y, h0, l0);
    split2(v.z, v.w, h1, l1);
    ((uint32_t*)hi)[i * 2 + 0] = h0;
    ((uint32_t*)hi)[i * 2 + 1] = h1;
    ((uint32_t*)lo)[i * 2 + 0] = l0;
    ((uint32_t*)lo)[i * 2 + 1] = l1;
}

// ---------------------------------------------------------------------------
// bf16x3 HMMA GEMM: C = (Ahi+Alo) @ (Bhi+Blo)^T + bias.
// Output either fp32 (Cf) or bf16 hi/lo (Chi/Clo) when Cf == nullptr.
// ---------------------------------------------------------------------------
#define KC      32
#define TSTR    80
#define TILE_B  (128 * TSTR)
#define BUF_B   (4 * TILE_B)
#define G_SMEM  (2 * BUF_B)

__global__ __launch_bounds__(256, 2) void gemm_bf16x3_kernel(
    const __nv_bfloat16* __restrict__ Ahi, const __nv_bfloat16* __restrict__ Alo,
    const __nv_bfloat16* __restrict__ Bhi, const __nv_bfloat16* __restrict__ Blo,
    const float* __restrict__ bias, float* __restrict__ Cf,
    __nv_bfloat16* __restrict__ Chi, __nv_bfloat16* __restrict__ Clo,
    int M, int N, int K)
{
    extern __shared__ char smraw[];
    const uint32_t sb = smem_u32(smraw);

    const int tid  = threadIdx.x;
    const int lane = tid & 31;
    const int wid  = tid >> 5;
    const int wm   = wid >> 1;
    const int wn   = wid & 1;
    const int m0 = blockIdx.y * 128;
    const int n0 = blockIdx.x * 128;

    const uint32_t a_row = lane & 15;
    const uint32_t a_kof = (lane >> 4) << 4;
    const uint32_t b_row = (lane & 7) | (((lane >> 4) & 1) << 3);
    const uint32_t b_kof = ((lane >> 3) & 1) << 4;

    float acc[2][8][4];
    #pragma unroll
    for (int i = 0; i < 2; i++)
        #pragma unroll
        for (int j = 0; j < 8; j++)
            #pragma unroll
            for (int c = 0; c < 4; c++) acc[i][j][c] = 0.0f;

    auto load_chunk = [&](int c, int b) {
        const int k0 = c * KC;
        const uint32_t bufb = sb + b * BUF_B;
        #pragma unroll
        for (int it = 0; it < 8; it++) {
            int idx = tid + it * 256;
            int t   = idx >> 9;
            int w   = idx & 511;
            int row = w >> 2;
            int seg = w & 3;
            const __nv_bfloat16* gp;
            if (t == 0)      gp = Ahi + (size_t)(m0 + row) * K + k0 + seg * 8;
            else if (t == 1) gp = Alo + (size_t)(m0 + row) * K + k0 + seg * 8;
            else if (t == 2) gp = Bhi + (size_t)(n0 + row) * K + k0 + seg * 8;
            else             gp = Blo + (size_t)(n0 + row) * K + k0 + seg * 8;
            cp_async16(bufb + t * TILE_B + row * TSTR + seg * 16, gp);
        }
        cp_commit();
    };

    const int nch = K / KC;
    load_chunk(0, 0);

    for (int i = 0; i < nch; i++) {
        if (i + 1 < nch) { load_chunk(i + 1, (i + 1) & 1); cp_wait<1>(); }
        else             { cp_wait<0>(); }
        __syncthreads();

        const uint32_t bufb = sb + (i & 1) * BUF_B;
        const uint32_t Aht = bufb;
        const uint32_t Alt = bufb + TILE_B;
        const uint32_t Bht = bufb + 2 * TILE_B;
        const uint32_t Blt = bufb + 3 * TILE_B;

        #pragma unroll
        for (int ks = 0; ks < 2; ks++) {
            const uint32_t kb = ks * 32;
            uint32_t ah[2][4], al[2][4];
            #pragma unroll
            for (int mi = 0; mi < 2; mi++) {
                uint32_t roff = (wm * 32 + mi * 16 + a_row) * TSTR + kb + a_kof;
                ldsm4(ah[mi], Aht + roff);
                ldsm4(al[mi], Alt + roff);
            }
            #pragma unroll
            for (int njp = 0; njp < 4; njp++) {
                uint32_t bh[4], bl[4];
                uint32_t roff = (wn * 64 + njp * 16 + b_row) * TSTR + kb + b_kof;
                ldsm4(bh, Bht + roff);
                ldsm4(bl, Blt + roff);
                #pragma unroll
                for (int mi = 0; mi < 2; mi++) {
                    mma16816(acc[mi][2 * njp],     ah[mi], bh);
                    mma16816(acc[mi][2 * njp],     al[mi], bh);
                    mma16816(acc[mi][2 * njp],     ah[mi], bl);
                    mma16816(acc[mi][2 * njp + 1], ah[mi], bh + 2);
                    mma16816(acc[mi][2 * njp + 1], al[mi], bh + 2);
                    mma16816(acc[mi][2 * njp + 1], ah[mi], bl + 2);
                }
            }
        }
        __syncthreads();
    }

    #pragma unroll
    for (int mi = 0; mi < 2; mi++) {
        int row = m0 + wm * 32 + mi * 16 + (lane >> 2);
        #pragma unroll
        for (int nj = 0; nj < 8; nj++) {
            int col = n0 + wn * 64 + nj * 8 + (lane & 3) * 2;
            float bx = bias[col], by = bias[col + 1];
            float v00 = acc[mi][nj][0] + bx, v01 = acc[mi][nj][1] + by;
            float v10 = acc[mi][nj][2] + bx, v11 = acc[mi][nj][3] + by;
            if (Cf) {
                *(float2*)(Cf + (size_t)row * N + col) = make_float2(v00, v01);
                *(float2*)(Cf + (size_t)(row + 8) * N + col) = make_float2(v10, v11);
            } else {
                uint32_t hi, lo;
                split2(v00, v01, hi, lo);
                *(uint32_t*)(Chi + (size_t)row * N + col) = hi;
                *(uint32_t*)(Clo + (size_t)row * N + col) = lo;
                split2(v10, v11, hi, lo);
                *(uint32_t*)(Chi + (size_t)(row + 8) * N + col) = hi;
                *(uint32_t*)(Clo + (size_t)(row + 8) * N + col) = lo;
            }
        }
    }
}

// ---------------------------------------------------------------------------
// Tensor-core causal flash attention (bf16x3 for S and PV, fp32 softmax).
// CTA: 128 queries x one (b,h); 8 warps, each owns m16 x 64 keys x 64 dims.
// smem: Qhi/Qlo [128][144B] + double-buffered Khi/Klo/Vhi/Vlo [64][144B].
// ---------------------------------------------------------------------------
#define ASTR   144
#define AQH    0
#define AQL    18432
#define AKH    36864
#define AKL    55296
#define AVH    73728
#define AVL    92160
#define AKVB   9216
#define A_SMEM 110592

__global__ __launch_bounds__(256, 2) void attn_mma_kernel(
    const __nv_bfloat16* __restrict__ qhi, const __nv_bfloat16* __restrict__ qlo,
    __nv_bfloat16* __restrict__ ohi, __nv_bfloat16* __restrict__ olo)
{
    extern __shared__ char smraw[];
    const uint32_t sb = smem_u32(smraw);

    const int b = blockIdx.z, h = blockIdx.y;
    const int q0 = ((int)gridDim.x - 1 - (int)blockIdx.x) * 128;  // heavy first
    const int tid = threadIdx.x, lane = tid & 31, w = tid >> 5;
    const int g = lane >> 2, t4 = lane & 3;

    // Prologue: Q tile (hi+lo), 128 rows x 8 segs x 2 = 8 cp.async/thread
    #pragma unroll
    for (int it = 0; it < 8; it++) {
        int idx = tid + it * 256;
        int hl  = idx >> 10;
        int wq  = idx & 1023;
        int row = wq >> 3, seg = wq & 7;
        const __nv_bfloat16* gp = (hl ? qlo : qhi)
            + (size_t)(b * T_DIM + q0 + row) * QKV_N + h * DH + seg * 8;
        cp_async16(sb + (hl ? AQL : AQH) + row * ASTR + seg * 16, gp);
    }

    auto load_kv = [&](int t, int buf) {
        const int k0 = t * 64;
        #pragma unroll
        for (int it = 0; it < 8; it++) {
            int idx = tid + it * 256;
            int which = idx >> 9;            // 0 Khi, 1 Klo, 2 Vhi, 3 Vlo
            int wq  = idx & 511;
            int row = wq >> 3, seg = wq & 7;
            size_t goff = (size_t)(b * T_DIM + k0 + row) * QKV_N + h * DH + seg * 8;
            const __nv_bfloat16* gp;
            uint32_t base;
            if (which == 0)      { gp = qhi + goff + C_DIM;     base = AKH; }
            else if (which == 1) { gp = qlo + goff + C_DIM;     base = AKL; }
            else if (which == 2) { gp = qhi + goff + 2 * C_DIM; base = AVH; }
            else                 { gp = qlo + goff + 2 * C_DIM; base = AVL; }
            cp_async16(sb + base + buf * AKVB + row * ASTR + seg * 16, gp);
        }
    };

    load_kv(0, 0);
    cp_commit();

    float O[8][4];
    #pragma unroll
    for (int j = 0; j < 8; j++)
        #pragma unroll
        for (int c = 0; c < 4; c++) O[j][c] = 0.0f;
    float m0 = -1e30f, m1 = -1e30f, l0 = 0.0f, l1 = 0.0f;

    // ldmatrix lane addressing
    const uint32_t a_off = (uint32_t)(w * 16 + (lane & 15)) * ASTR + ((lane >> 4) << 4);
    const uint32_t b_row = (uint32_t)((lane & 7) | (((lane >> 4) & 1) << 3));
    const uint32_t b_kof = ((lane >> 3) & 1) << 4;
    const uint32_t v_off = (uint32_t)(lane & 15) * ASTR + ((lane >> 4) << 4);

    const int ntiles = (q0 >> 6) + 2;
    for (int t = 0; t < ntiles; t++) {
        if (t + 1 < ntiles) { load_kv(t + 1, (t + 1) & 1); cp_commit(); cp_wait<1>(); }
        else                { cp_wait<0>(); }
        __syncthreads();
        const uint32_t kb = (t & 1) * AKVB;

        // ---- S = Q @ K^T (bf16x3) ----
        float S[8][4];
        #pragma unroll
        for (int j = 0; j < 8; j++)
            #pragma unroll
            for (int c = 0; c < 4; c++) S[j][c] = 0.0f;

        #pragma unroll
        for (int ks = 0; ks < 4; ks++) {
            uint32_t qh[4], ql[4];
            ldsm4(qh, sb + AQH + a_off + ks * 32);
            ldsm4(ql, sb + AQL + a_off + ks * 32);
            #pragma unroll
            for (int jg = 0; jg < 4; jg++) {
                uint32_t kh[4], kl[4];
                uint32_t ro = (jg * 16 + b_row) * ASTR + ks * 32 + b_kof;
                ldsm4(kh, sb + AKH + kb + ro);
                ldsm4(kl, sb + AKL + kb + ro);
                mma16816(S[2 * jg],     qh, kh);
                mma16816(S[2 * jg],     ql, kh);
                mma16816(S[2 * jg],     qh, kl);
                mma16816(S[2 * jg + 1], qh, kh + 2);
                mma16816(S[2 * jg + 1], ql, kh + 2);
                mma16816(S[2 * jg + 1], qh, kl + 2);
            }
        }

        // ---- scale + causal mask ----
        const int k0 = t * 64;
        const int qw = q0 + w * 16;
        #pragma unroll
        for (int j = 0; j < 8; j++)
            #pragma unroll
            for (int c = 0; c < 4; c++) S[j][c] *= 0.125f;
        if (k0 + 64 > qw) {
            const int r0 = qw + g, r1 = qw + g + 8;
            #pragma unroll
            for (int j = 0; j < 8; j++) {
                int key = k0 + j * 8 + t4 * 2;
                if (key     > r0) S[j][0] = -1e30f;
                if (key + 1 > r0) S[j][1] = -1e30f;
                if (key     > r1) S[j][2] = -1e30f;
                if (key + 1 > r1) S[j][3] = -1e30f;
            }
        }

        // ---- online softmax (rows g and g+8, quad shfl reduce) ----
        float mx0 = -1e30f, mx1 = -1e30f;
        #pragma unroll
        for (int j = 0; j < 8; j++) {
            mx0 = fmaxf(mx0, fmaxf(S[j][0], S[j][1]));
            mx1 = fmaxf(mx1, fmaxf(S[j][2], S[j][3]));
        }
        mx0 = fmaxf(mx0, __shfl_xor_sync(0xffffffffu, mx0, 1));
        mx0 = fmaxf(mx0, __shfl_xor_sync(0xffffffffu, mx0, 2));
        mx1 = fmaxf(mx1, __shfl_xor_sync(0xffffffffu, mx1, 1));
        mx1 = fmaxf(mx1, __shfl_xor_sync(0xffffffffu, mx1, 2));
        float nm0 = fmaxf(m0, mx0), nm1 = fmaxf(m1, mx1);
        float c0 = __expf(m0 - nm0), c1 = __expf(m1 - nm1);
        float s0 = 0.0f, s1 = 0.0f;
        #pragma unroll
        for (int j = 0; j < 8; j++) {
            S[j][0] = __expf(S[j][0] - nm0); s0 += S[j][0];
            S[j][1] = __expf(S[j][1] - nm0); s0 += S[j][1];
            S[j][2] = __expf(S[j][2] - nm1); s1 += S[j][2];
            S[j][3] = __expf(S[j][3] - nm1); s1 += S[j][3];
        }
        s0 += __shfl_xor_sync(0xffffffffu, s0, 1);
        s0 += __shfl_xor_sync(0xffffffffu, s0, 2);
        s1 += __shfl_xor_sync(0xffffffffu, s1, 1);
        s1 += __shfl_xor_sync(0xffffffffu, s1, 2);
        l0 = l0 * c0 + s0; l1 = l1 * c1 + s1;
        m0 = nm0; m1 = nm1;
        #pragma unroll
        for (int j = 0; j < 8; j++) {
            O[j][0] *= c0; O[j][1] *= c0;
            O[j][2] *= c1; O[j][3] *= c1;
        }

        // ---- pack P into PV A-fragments (hi + residual lo) ----
        uint32_t Ph[4][4], Pl[4][4];
        #pragma unroll
        for (int ks = 0; ks < 4; ks++) {
            split2(S[2 * ks][0],     S[2 * ks][1],     Ph[ks][0], Pl[ks][0]);
            split2(S[2 * ks][2],     S[2 * ks][3],     Ph[ks][1], Pl[ks][1]);
            split2(S[2 * ks + 1][0], S[2 * ks + 1][1], Ph[ks][2], Pl[ks][2]);
            split2(S[2 * ks + 1][2], S[2 * ks + 1][3], Ph[ks][3], Pl[ks][3]);
        }

        // ---- O += P @ V (bf16x3), V via ldmatrix.trans ----
        #pragma unroll
        for (int ks = 0; ks < 4; ks++) {
            #pragma unroll
            for (int db = 0; db < 4; db++) {
                uint32_t vh[4], vl[4];
                uint32_t vo = kb + (uint32_t)ks * 16 * ASTR + v_off + db * 32;
                ldsm4t(vh, sb + AVH + vo);
                ldsm4t(vl, sb + AVL + vo);
                mma16816(O[2 * db],     Ph[ks], vh);
                mma16816(O[2 * db],     Pl[ks], vh);
                mma16816(O[2 * db],     Ph[ks], vl);
                mma16816(O[2 * db + 1], Ph[ks], vh + 2);
                mma16816(O[2 * db + 1], Pl[ks], vh + 2);
                mma16816(O[2 * db + 1], Ph[ks], vl + 2);
            }
        }
        __syncthreads();
    }

    // ---- epilogue: normalize, split hi/lo, store ----
    const float inv0 = 1.0f / l0, inv1 = 1.0f / l1;
    const size_t r0 = (size_t)(b * T_DIM + q0 + w * 16 + g) * C_DIM + h * DH;
    const size_t r1 = r0 + 8 * C_DIM;
    #pragma unroll
    for (int j = 0; j < 8; j++) {
        int col = j * 8 + t4 * 2;
        uint32_t hi, lo;
        split2(O[j][0] * inv0, O[j][1] * inv0, hi, lo);
        *(uint32_t*)(ohi + r0 + col) = hi;
        *(uint32_t*)(olo + r0 + col) = lo;
        split2(O[j][2] * inv1, O[j][3] * inv1, hi, lo);
        *(uint32_t*)(ohi + r1 + col) = hi;
        *(uint32_t*)(olo + r1 + col) = lo;
    }
}

// ---------------------------------------------------------------------------
// Launch
// ---------------------------------------------------------------------------
extern "C" void kernel_launch(void* const* d_in, const int* in_sizes, int n_in,
                              void* d_out, int out_size)
{
    const float* x    = (const float*)d_in[0];
    const float* Wqkv = (const float*)d_in[1];
    const float* bqkv = (const float*)d_in[2];
    const float* Wo   = (const float*)d_in[3];
    const float* bo   = (const float*)d_in[4];
    float* out = (float*)d_out;

    __nv_bfloat16 *qkvhi, *qkvlo, *xhi, *xlo, *wqh, *wql, *woh, *wol, *ahi, *alo;
    cudaGetSymbolAddress((void**)&qkvhi, g_qkvhi);
    cudaGetSymbolAddress((void**)&qkvlo, g_qkvlo);
    cudaGetSymbolAddress((void**)&xhi, g_xhi);
    cudaGetSymbolAddress((void**)&xlo, g_xlo);
    cudaGetSymbolAddress((void**)&wqh, g_wqkv_hi);
    cudaGetSymbolAddress((void**)&wql, g_wqkv_lo);
    cudaGetSymbolAddress((void**)&woh, g_wo_hi);
    cudaGetSymbolAddress((void**)&wol, g_wo_lo);
    cudaGetSymbolAddress((void**)&ahi, g_ahi);
    cudaGetSymbolAddress((void**)&alo, g_alo);

    cudaFuncSetAttribute(gemm_bf16x3_kernel,
                         cudaFuncAttributeMaxDynamicSharedMemorySize, G_SMEM);
    cudaFuncSetAttribute(attn_mma_kernel,
                         cudaFuncAttributeMaxDynamicSharedMemorySize, A_SMEM);

    split_kernel<<<(NTOK * C_DIM / 4 + 255) / 256, 256>>>(x, xhi, xlo, NTOK * C_DIM / 4);
    split_kernel<<<(QKV_N * C_DIM / 4 + 255) / 256, 256>>>(Wqkv, wqh, wql, QKV_N * C_DIM / 4);
    split_kernel<<<(C_DIM * C_DIM / 4 + 255) / 256, 256>>>(Wo, woh, wol, C_DIM * C_DIM / 4);

    // qkv (bf16 hi/lo) = x @ Wqkv^T + bqkv
    gemm_bf16x3_kernel<<<dim3(QKV_N / 128, NTOK / 128), 256, G_SMEM>>>(
        xhi, xlo, wqh, wql, bqkv, nullptr, qkvhi, qkvlo, NTOK, QKV_N, C_DIM);

    // attention -> bf16 hi/lo
    attn_mma_kernel<<<dim3(T_DIM / 128, H_DIM, B_DIM), 256, A_SMEM>>>(
        qkvhi, qkvlo, ahi, alo);

    // out (fp32) = attn @ Wo^T + bo
    gemm_bf16x3_kernel<<<dim3(C_DIM / 128, NTOK / 128), 256, G_SMEM>>>(
        ahi, alo, woh, wol, bo, out, nullptr, nullptr, NTOK, C_DIM, C_DIM);
}

// round 6
// speedup vs baseline: 3.1261x; 1.0317x over previous
#include <cuda_runtime.h>
#include <cuda_bf16.h>
#include <cstdint>

// Problem constants
#define B_DIM 4
#define T_DIM 2048
#define C_DIM 1024
#define H_DIM 16
#define DH    64
#define NTOK  8192
#define QKV_N 3072

// Static device scratch (no cudaMalloc allowed)
__device__ __nv_bfloat16 g_qkvhi[(size_t)NTOK * QKV_N];
__device__ __nv_bfloat16 g_qkvlo[(size_t)NTOK * QKV_N];
__device__ __nv_bfloat16 g_xhi[(size_t)NTOK * C_DIM];
__device__ __nv_bfloat16 g_xlo[(size_t)NTOK * C_DIM];
__device__ __nv_bfloat16 g_wqkv_hi[(size_t)QKV_N * C_DIM];
__device__ __nv_bfloat16 g_wqkv_lo[(size_t)QKV_N * C_DIM];
__device__ __nv_bfloat16 g_wo_hi[(size_t)C_DIM * C_DIM];
__device__ __nv_bfloat16 g_wo_lo[(size_t)C_DIM * C_DIM];
__device__ __nv_bfloat16 g_ahi[(size_t)NTOK * C_DIM];
__device__ __nv_bfloat16 g_alo[(size_t)NTOK * C_DIM];

// ---------------------------------------------------------------------------
// Helpers (base sm_100: cp.async, ldmatrix, mma.sync)
// ---------------------------------------------------------------------------
static __device__ __forceinline__ uint32_t smem_u32(const void* p) {
    uint32_t a;
    asm("{ .reg .u64 t; cvta.to.shared.u64 t, %1; cvt.u32.u64 %0, t; }"
        : "=r"(a) : "l"(p));
    return a;
}
static __device__ __forceinline__ void cp_async16(uint32_t s, const void* g) {
    asm volatile("cp.async.ca.shared.global [%0], [%1], 16;" :: "r"(s), "l"(g));
}
static __device__ __forceinline__ void cp_commit() {
    asm volatile("cp.async.commit_group;" ::: "memory");
}
template <int N> static __device__ __forceinline__ void cp_wait() {
    asm volatile("cp.async.wait_group %0;" :: "n"(N) : "memory");
}
static __device__ __forceinline__ void ldsm4(uint32_t* r, uint32_t addr) {
    asm volatile("ldmatrix.sync.aligned.m8n8.x4.shared.b16 {%0,%1,%2,%3}, [%4];"
        : "=r"(r[0]), "=r"(r[1]), "=r"(r[2]), "=r"(r[3]) : "r"(addr));
}
static __device__ __forceinline__ void ldsm4t(uint32_t* r, uint32_t addr) {
    asm volatile("ldmatrix.sync.aligned.m8n8.x4.trans.shared.b16 {%0,%1,%2,%3}, [%4];"
        : "=r"(r[0]), "=r"(r[1]), "=r"(r[2]), "=r"(r[3]) : "r"(addr));
}
// NOTE: non-volatile -> ptxas may schedule/interleave these freely.
static __device__ __forceinline__ void mma16816(float* c, const uint32_t* a,
                                                const uint32_t* b) {
    asm("mma.sync.aligned.m16n8k16.row.col.f32.bf16.bf16.f32 "
        "{%0,%1,%2,%3}, {%4,%5,%6,%7}, {%8,%9}, {%0,%1,%2,%3};"
        : "+f"(c[0]), "+f"(c[1]), "+f"(c[2]), "+f"(c[3])
        : "r"(a[0]), "r"(a[1]), "r"(a[2]), "r"(a[3]), "r"(b[0]), "r"(b[1]));
}
// Split two fp32 into packed bf16x2 hi + bf16x2 lo (lo = residual)
static __device__ __forceinline__ void split2(float a, float b,
                                              uint32_t& hi, uint32_t& lo) {
    __nv_bfloat16 ha = __float2bfloat16(a), hb = __float2bfloat16(b);
    float ra = a - __bfloat162float(ha);
    float rb = b - __bfloat162float(hb);
    __nv_bfloat162 H(ha, hb);
    __nv_bfloat162 L(__float2bfloat16(ra), __float2bfloat16(rb));
    hi = *(uint32_t*)&H; lo = *(uint32_t*)&L;
}

// ---------------------------------------------------------------------------
// Split fp32 -> bf16 hi/lo (memory-bound)
// ---------------------------------------------------------------------------
__global__ __launch_bounds__(256) void split_kernel(
    const float* __restrict__ src, __nv_bfloat16* __restrict__ hi,
    __nv_bfloat16* __restrict__ lo, int n4)
{
    int i = blockIdx.x * blockDim.x + threadIdx.x;
    if (i >= n4) return;
    float4 v = ((const float4*)src)[i];
    uint32_t h0, l0, h1, l1;
    split2(v.x, v.y, h0, l0);
    split2(v.z, v.w, h1, l1);
    ((uint32_t*)hi)[i * 2 + 0] = h0;
    ((uint32_t*)hi)[i * 2 + 1] = h1;
    ((uint32_t*)lo)[i * 2 + 0] = l0;
    ((uint32_t*)lo)[i * 2 + 1] = l1;
}

// ---------------------------------------------------------------------------
// bf16x3 HMMA GEMM: C = (Ahi+Alo) @ (Bhi+Blo)^T + bias.
// Inner loop runs the 3 split terms as separate passes so consecutive mma
// target distinct accumulators (16 independent mma between same-acc reuse).
// ---------------------------------------------------------------------------
#define KC      32
#define TSTR    80
#define TILE_B  (128 * TSTR)
#define BUF_B   (4 * TILE_B)
#define G_SMEM  (2 * BUF_B)

__global__ __launch_bounds__(256, 2) void gemm_bf16x3_kernel(
    const __nv_bfloat16* __restrict__ Ahi, const __nv_bfloat16* __restrict__ Alo,
    const __nv_bfloat16* __restrict__ Bhi, const __nv_bfloat16* __restrict__ Blo,
    const float* __restrict__ bias, float* __restrict__ Cf,
    __nv_bfloat16* __restrict__ Chi, __nv_bfloat16* __restrict__ Clo,
    int M, int N, int K)
{
    extern __shared__ char smraw[];
    const uint32_t sb = smem_u32(smraw);

    const int tid  = threadIdx.x;
    const int lane = tid & 31;
    const int wid  = tid >> 5;
    const int wm   = wid >> 1;
    const int wn   = wid & 1;
    const int m0 = blockIdx.y * 128;
    const int n0 = blockIdx.x * 128;

    const uint32_t a_row = lane & 15;
    const uint32_t a_kof = (lane >> 4) << 4;
    const uint32_t b_row = (lane & 7) | (((lane >> 4) & 1) << 3);
    const uint32_t b_kof = ((lane >> 3) & 1) << 4;

    float acc[2][8][4];
    #pragma unroll
    for (int i = 0; i < 2; i++)
        #pragma unroll
        for (int j = 0; j < 8; j++)
            #pragma unroll
            for (int c = 0; c < 4; c++) acc[i][j][c] = 0.0f;

    auto load_chunk = [&](int c, int b) {
        const int k0 = c * KC;
        const uint32_t bufb = sb + b * BUF_B;
        #pragma unroll
        for (int it = 0; it < 8; it++) {
            int idx = tid + it * 256;
            int t   = idx >> 9;
            int w   = idx & 511;
            int row = w >> 2;
            int seg = w & 3;
            const __nv_bfloat16* gp;
            if (t == 0)      gp = Ahi + (size_t)(m0 + row) * K + k0 + seg * 8;
            else if (t == 1) gp = Alo + (size_t)(m0 + row) * K + k0 + seg * 8;
            else if (t == 2) gp = Bhi + (size_t)(n0 + row) * K + k0 + seg * 8;
            else             gp = Blo + (size_t)(n0 + row) * K + k0 + seg * 8;
            cp_async16(bufb + t * TILE_B + row * TSTR + seg * 16, gp);
        }
        cp_commit();
    };

    const int nch = K / KC;
    load_chunk(0, 0);

    for (int i = 0; i < nch; i++) {
        if (i + 1 < nch) { load_chunk(i + 1, (i + 1) & 1); cp_wait<1>(); }
        else             { cp_wait<0>(); }
        __syncthreads();

        const uint32_t bufb = sb + (i & 1) * BUF_B;
        const uint32_t Aht = bufb;
        const uint32_t Alt = bufb + TILE_B;
        const uint32_t Bht = bufb + 2 * TILE_B;
        const uint32_t Blt = bufb + 3 * TILE_B;

        #pragma unroll
        for (int ks = 0; ks < 2; ks++) {
            const uint32_t kb = ks * 32;
            uint32_t ah[2][4], al[2][4], bb[4][4];
            #pragma unroll
            for (int mi = 0; mi < 2; mi++) {
                uint32_t roff = (wm * 32 + mi * 16 + a_row) * TSTR + kb + a_kof;
                ldsm4(ah[mi], Aht + roff);
                ldsm4(al[mi], Alt + roff);
            }
            #pragma unroll
            for (int njp = 0; njp < 4; njp++)
                ldsm4(bb[njp], Bht + (wn * 64 + njp * 16 + b_row) * TSTR + kb + b_kof);

            // pass 1: Ahi * Bhi  (16 independent mma)
            #pragma unroll
            for (int njp = 0; njp < 4; njp++)
                #pragma unroll
                for (int mi = 0; mi < 2; mi++) {
                    mma16816(acc[mi][2 * njp],     ah[mi], bb[njp]);
                    mma16816(acc[mi][2 * njp + 1], ah[mi], bb[njp] + 2);
                }
            // pass 2: Alo * Bhi
            #pragma unroll
            for (int njp = 0; njp < 4; njp++)
                #pragma unroll
                for (int mi = 0; mi < 2; mi++) {
                    mma16816(acc[mi][2 * njp],     al[mi], bb[njp]);
                    mma16816(acc[mi][2 * njp + 1], al[mi], bb[njp] + 2);
                }
            // reload B lo, pass 3: Ahi * Blo
            #pragma unroll
            for (int njp = 0; njp < 4; njp++)
                ldsm4(bb[njp], Blt + (wn * 64 + njp * 16 + b_row) * TSTR + kb + b_kof);
            #pragma unroll
            for (int njp = 0; njp < 4; njp++)
                #pragma unroll
                for (int mi = 0; mi < 2; mi++) {
                    mma16816(acc[mi][2 * njp],     ah[mi], bb[njp]);
                    mma16816(acc[mi][2 * njp + 1], ah[mi], bb[njp] + 2);
                }
        }
        __syncthreads();
    }

    #pragma unroll
    for (int mi = 0; mi < 2; mi++) {
        int row = m0 + wm * 32 + mi * 16 + (lane >> 2);
        #pragma unroll
        for (int nj = 0; nj < 8; nj++) {
            int col = n0 + wn * 64 + nj * 8 + (lane & 3) * 2;
            float bx = bias[col], by = bias[col + 1];
            float v00 = acc[mi][nj][0] + bx, v01 = acc[mi][nj][1] + by;
            float v10 = acc[mi][nj][2] + bx, v11 = acc[mi][nj][3] + by;
            if (Cf) {
                *(float2*)(Cf + (size_t)row * N + col) = make_float2(v00, v01);
                *(float2*)(Cf + (size_t)(row + 8) * N + col) = make_float2(v10, v11);
            } else {
                uint32_t hi, lo;
                split2(v00, v01, hi, lo);
                *(uint32_t*)(Chi + (size_t)row * N + col) = hi;
                *(uint32_t*)(Clo + (size_t)row * N + col) = lo;
                split2(v10, v11, hi, lo);
                *(uint32_t*)(Chi + (size_t)(row + 8) * N + col) = hi;
                *(uint32_t*)(Clo + (size_t)(row + 8) * N + col) = lo;
            }
        }
    }
}

// ---------------------------------------------------------------------------
// Tensor-core causal flash attention (bf16x3 for S and PV, fp32 softmax).
// Same per-term pass restructuring as the GEMM.
// ---------------------------------------------------------------------------
#define ASTR   144
#define AQH    0
#define AQL    18432
#define AKH    36864
#define AKL    55296
#define AVH    73728
#define AVL    92160
#define AKVB   9216
#define A_SMEM 110592

__global__ __launch_bounds__(256, 2) void attn_mma_kernel(
    const __nv_bfloat16* __restrict__ qhi, const __nv_bfloat16* __restrict__ qlo,
    __nv_bfloat16* __restrict__ ohi, __nv_bfloat16* __restrict__ olo)
{
    extern __shared__ char smraw[];
    const uint32_t sb = smem_u32(smraw);

    const int b = blockIdx.z, h = blockIdx.y;
    const int q0 = ((int)gridDim.x - 1 - (int)blockIdx.x) * 128;  // heavy first
    const int tid = threadIdx.x, lane = tid & 31, w = tid >> 5;
    const int g = lane >> 2, t4 = lane & 3;

    #pragma unroll
    for (int it = 0; it < 8; it++) {
        int idx = tid + it * 256;
        int hl  = idx >> 10;
        int wq  = idx & 1023;
        int row = wq >> 3, seg = wq & 7;
        const __nv_bfloat16* gp = (hl ? qlo : qhi)
            + (size_t)(b * T_DIM + q0 + row) * QKV_N + h * DH + seg * 8;
        cp_async16(sb + (hl ? AQL : AQH) + row * ASTR + seg * 16, gp);
    }

    auto load_kv = [&](int t, int buf) {
        const int k0 = t * 64;
        #pragma unroll
        for (int it = 0; it < 8; it++) {
            int idx = tid + it * 256;
            int which = idx >> 9;
            int wq  = idx & 511;
            int row = wq >> 3, seg = wq & 7;
            size_t goff = (size_t)(b * T_DIM + k0 + row) * QKV_N + h * DH + seg * 8;
            const __nv_bfloat16* gp;
            uint32_t base;
            if (which == 0)      { gp = qhi + goff + C_DIM;     base = AKH; }
            else if (which == 1) { gp = qlo + goff + C_DIM;     base = AKL; }
            else if (which == 2) { gp = qhi + goff + 2 * C_DIM; base = AVH; }
            else                 { gp = qlo + goff + 2 * C_DIM; base = AVL; }
            cp_async16(sb + base + buf * AKVB + row * ASTR + seg * 16, gp);
        }
    };

    load_kv(0, 0);
    cp_commit();

    float O[8][4];
    #pragma unroll
    for (int j = 0; j < 8; j++)
        #pragma unroll
        for (int c = 0; c < 4; c++) O[j][c] = 0.0f;
    float m0 = -1e30f, m1 = -1e30f, l0 = 0.0f, l1 = 0.0f;

    const uint32_t a_off = (uint32_t)(w * 16 + (lane & 15)) * ASTR + ((lane >> 4) << 4);
    const uint32_t b_row = (uint32_t)((lane & 7) | (((lane >> 4) & 1) << 3));
    const uint32_t b_kof = ((lane >> 3) & 1) << 4;
    const uint32_t v_off = (uint32_t)(lane & 15) * ASTR + ((lane >> 4) << 4);

    const int ntiles = (q0 >> 6) + 2;
    for (int t = 0; t < ntiles; t++) {
        if (t + 1 < ntiles) { load_kv(t + 1, (t + 1) & 1); cp_commit(); cp_wait<1>(); }
        else                { cp_wait<0>(); }
        __syncthreads();
        const uint32_t kb = (t & 1) * AKVB;

        // ---- S = Q @ K^T (bf16x3, per-term passes) ----
        float S[8][4];
        #pragma unroll
        for (int j = 0; j < 8; j++)
            #pragma unroll
            for (int c = 0; c < 4; c++) S[j][c] = 0.0f;

        #pragma unroll
        for (int ks = 0; ks < 4; ks++) {
            uint32_t qh[4], ql[4], kk[4][4];
            ldsm4(qh, sb + AQH + a_off + ks * 32);
            ldsm4(ql, sb + AQL + a_off + ks * 32);
            #pragma unroll
            for (int jg = 0; jg < 4; jg++)
                ldsm4(kk[jg], sb + AKH + kb + (jg * 16 + b_row) * ASTR + ks * 32 + b_kof);
            #pragma unroll
            for (int jg = 0; jg < 4; jg++) {
                mma16816(S[2 * jg],     qh, kk[jg]);
                mma16816(S[2 * jg + 1], qh, kk[jg] + 2);
            }
            #pragma unroll
            for (int jg = 0; jg < 4; jg++) {
                mma16816(S[2 * jg],     ql, kk[jg]);
                mma16816(S[2 * jg + 1], ql, kk[jg] + 2);
            }
            #pragma unroll
            for (int jg = 0; jg < 4; jg++)
                ldsm4(kk[jg], sb + AKL + kb + (jg * 16 + b_row) * ASTR + ks * 32 + b_kof);
            #pragma unroll
            for (int jg = 0; jg < 4; jg++) {
                mma16816(S[2 * jg],     qh, kk[jg]);
                mma16816(S[2 * jg + 1], qh, kk[jg] + 2);
            }
        }

        // ---- scale + causal mask ----
        const int k0 = t * 64;
        const int qw = q0 + w * 16;
        #pragma unroll
        for (int j = 0; j < 8; j++)
            #pragma unroll
            for (int c = 0; c < 4; c++) S[j][c] *= 0.125f;
        if (k0 + 64 > qw) {
            const int r0 = qw + g, r1 = qw + g + 8;
            #pragma unroll
            for (int j = 0; j < 8; j++) {
                int key = k0 + j * 8 + t4 * 2;
                if (key     > r0) S[j][0] = -1e30f;
                if (key + 1 > r0) S[j][1] = -1e30f;
                if (key     > r1) S[j][2] = -1e30f;
                if (key + 1 > r1) S[j][3] = -1e30f;
            }
        }

        // ---- online softmax ----
        float mx0 = -1e30f, mx1 = -1e30f;
        #pragma unroll
        for (int j = 0; j < 8; j++) {
            mx0 = fmaxf(mx0, fmaxf(S[j][0], S[j][1]));
            mx1 = fmaxf(mx1, fmaxf(S[j][2], S[j][3]));
        }
        mx0 = fmaxf(mx0, __shfl_xor_sync(0xffffffffu, mx0, 1));
        mx0 = fmaxf(mx0, __shfl_xor_sync(0xffffffffu, mx0, 2));
        mx1 = fmaxf(mx1, __shfl_xor_sync(0xffffffffu, mx1, 1));
        mx1 = fmaxf(mx1, __shfl_xor_sync(0xffffffffu, mx1, 2));
        float nm0 = fmaxf(m0, mx0), nm1 = fmaxf(m1, mx1);
        float c0 = __expf(m0 - nm0), c1 = __expf(m1 - nm1);
        float s0 = 0.0f, s1 = 0.0f;
        #pragma unroll
        for (int j = 0; j < 8; j++) {
            S[j][0] = __expf(S[j][0] - nm0); s0 += S[j][0];
            S[j][1] = __expf(S[j][1] - nm0); s0 += S[j][1];
            S[j][2] = __expf(S[j][2] - nm1); s1 += S[j][2];
            S[j][3] = __expf(S[j][3] - nm1); s1 += S[j][3];
        }
        s0 += __shfl_xor_sync(0xffffffffu, s0, 1);
        s0 += __shfl_xor_sync(0xffffffffu, s0, 2);
        s1 += __shfl_xor_sync(0xffffffffu, s1, 1);
        s1 += __shfl_xor_sync(0xffffffffu, s1, 2);
        l0 = l0 * c0 + s0; l1 = l1 * c1 + s1;
        m0 = nm0; m1 = nm1;
        #pragma unroll
        for (int j = 0; j < 8; j++) {
            O[j][0] *= c0; O[j][1] *= c0;
            O[j][2] *= c1; O[j][3] *= c1;
        }

        // ---- pack P into PV A-fragments (hi + residual lo) ----
        uint32_t Ph[4][4], Pl[4][4];
        #pragma unroll
        for (int ks = 0; ks < 4; ks++) {
            split2(S[2 * ks][0],     S[2 * ks][1],     Ph[ks][0], Pl[ks][0]);
            split2(S[2 * ks][2],     S[2 * ks][3],     Ph[ks][1], Pl[ks][1]);
            split2(S[2 * ks + 1][0], S[2 * ks + 1][1], Ph[ks][2], Pl[ks][2]);
            split2(S[2 * ks + 1][2], S[2 * ks + 1][3], Ph[ks][3], Pl[ks][3]);
        }

        // ---- O += P @ V (bf16x3, per-term passes) ----
        #pragma unroll
        for (int ks = 0; ks < 4; ks++) {
            uint32_t vv[4][4];
            #pragma unroll
            for (int db = 0; db < 4; db++)
                ldsm4t(vv[db], sb + AVH + kb + (uint32_t)ks * 16 * ASTR + v_off + db * 32);
            #pragma unroll
            for (int db = 0; db < 4; db++) {
                mma16816(O[2 * db],     Ph[ks], vv[db]);
                mma16816(O[2 * db + 1], Ph[ks], vv[db] + 2);
            }
            #pragma unroll
            for (int db = 0; db < 4; db++) {
                mma16816(O[2 * db],     Pl[ks], vv[db]);
                mma16816(O[2 * db + 1], Pl[ks], vv[db] + 2);
            }
            #pragma unroll
            for (int db = 0; db < 4; db++)
                ldsm4t(vv[db], sb + AVL + kb + (uint32_t)ks * 16 * ASTR + v_off + db * 32);
            #pragma unroll
            for (int db = 0; db < 4; db++) {
                mma16816(O[2 * db],     Ph[ks], vv[db]);
                mma16816(O[2 * db + 1], Ph[ks], vv[db] + 2);
            }
        }
        __syncthreads();
    }

    // ---- epilogue ----
    const float inv0 = 1.0f / l0, inv1 = 1.0f / l1;
    const size_t r0 = (size_t)(b * T_DIM + q0 + w * 16 + g) * C_DIM + h * DH;
    const size_t r1 = r0 + 8 * C_DIM;
    #pragma unroll
    for (int j = 0; j < 8; j++) {
        int col = j * 8 + t4 * 2;
        uint32_t hi, lo;
        split2(O[j][0] * inv0, O[j][1] * inv0, hi, lo);
        *(uint32_t*)(ohi + r0 + col) = hi;
        *(uint32_t*)(olo + r0 + col) = lo;
        split2(O[j][2] * inv1, O[j][3] * inv1, hi, lo);
        *(uint32_t*)(ohi + r1 + col) = hi;
        *(uint32_t*)(olo + r1 + col) = lo;
    }
}

// ---------------------------------------------------------------------------
// Launch
// ---------------------------------------------------------------------------
extern "C" void kernel_launch(void* const* d_in, const int* in_sizes, int n_in,
                              void* d_out, int out_size)
{
    const float* x    = (const float*)d_in[0];
    const float* Wqkv = (const float*)d_in[1];
    const float* bqkv = (const float*)d_in[2];
    const float* Wo   = (const float*)d_in[3];
    const float* bo   = (const float*)d_in[4];
    float* out = (float*)d_out;

    __nv_bfloat16 *qkvhi, *qkvlo, *xhi, *xlo, *wqh, *wql, *woh, *wol, *ahi, *alo;
    cudaGetSymbolAddress((void**)&qkvhi, g_qkvhi);
    cudaGetSymbolAddress((void**)&qkvlo, g_qkvlo);
    cudaGetSymbolAddress((void**)&xhi, g_xhi);
    cudaGetSymbolAddress((void**)&xlo, g_xlo);
    cudaGetSymbolAddress((void**)&wqh, g_wqkv_hi);
    cudaGetSymbolAddress((void**)&wql, g_wqkv_lo);
    cudaGetSymbolAddress((void**)&woh, g_wo_hi);
    cudaGetSymbolAddress((void**)&wol, g_wo_lo);
    cudaGetSymbolAddress((void**)&ahi, g_ahi);
    cudaGetSymbolAddress((void**)&alo, g_alo);

    cudaFuncSetAttribute(gemm_bf16x3_kernel,
                         cudaFuncAttributeMaxDynamicSharedMemorySize, G_SMEM);
    cudaFuncSetAttribute(attn_mma_kernel,
                         cudaFuncAttributeMaxDynamicSharedMemorySize, A_SMEM);

    split_kernel<<<(NTOK * C_DIM / 4 + 255) / 256, 256>>>(x, xhi, xlo, NTOK * C_DIM / 4);
    split_kernel<<<(QKV_N * C_DIM / 4 + 255) / 256, 256>>>(Wqkv, wqh, wql, QKV_N * C_DIM / 4);
    split_kernel<<<(C_DIM * C_DIM / 4 + 255) / 256, 256>>>(Wo, woh, wol, C_DIM * C_DIM / 4);

    gemm_bf16x3_kernel<<<dim3(QKV_N / 128, NTOK / 128), 256, G_SMEM>>>(
        xhi, xlo, wqh, wql, bqkv, nullptr, qkvhi, qkvlo, NTOK, QKV_N, C_DIM);

    attn_mma_kernel<<<dim3(T_DIM / 128, H_DIM, B_DIM), 256, A_SMEM>>>(
        qkvhi, qkvlo, ahi, alo);

    gemm_bf16x3_kernel<<<dim3(C_DIM / 128, NTOK / 128), 256, G_SMEM>>>(
        ahi, alo, woh, wol, bo, out, nullptr, nullptr, NTOK, C_DIM, C_DIM);
}